// round 13
// baseline (speedup 1.0000x reference)
#include <cuda_runtime.h>

// FiringRateModel: T-step scalar-feedback linear recurrence, B independent chains.
//
// KEY CHANGE vs R12: remove f(t-1) from the wide update via substitution
// Vt(t) = V(t) - f(t-1)*D2B  (V = D^2∘u, u = v.*w/100):
//   Vt(t) = D∘Vt(t-1) + c_t*D2A + f(t-2)*D3B      <- consumes f(t-2), one body old!
//   z(t)  = SVt(t-2) + f(t-3)*SD2B + c_t*SA + c_{t-1}*SDA
//           + f(t-1)*SB + f(t-2)*SDB - gb
//   f(t)  = max(0, 200 - 400/(1 + 2^(K*poly(z))))
//
// R12 evidence: issue pinned at exactly 51.1% across 4 different kernels =
// each warp serial at ~290 cyc/step. Cause: the wide update consumed fn(t-1)
// near the body top, so in-order issue drained the pipe every step (body t+1
// couldn't start until body t's ex2->rcp->fn tail finished). Now fn(t-1) is
// consumed ONLY by phi, placed at the body END -- ~140 issue-cycles of
// independent work (wide on f(t-2), pipelined shfl reduction, tree) stand
// between fn's production and its consumption.
//
// R=4 lanes/chain, TPB=256, grid=128 -> 2 warps/SMSP.

#define TPB 256

typedef unsigned long long u64p;

__device__ __forceinline__ u64p pk2(float lo, float hi) {
    u64p r;
    asm("mov.b64 %0, {%1,%2};" : "=l"(r) : "r"(__float_as_uint(lo)), "r"(__float_as_uint(hi)));
    return r;
}
__device__ __forceinline__ void upk2(u64p v, float &lo, float &hi) {
    unsigned int l, h;
    asm("mov.b64 {%0,%1}, %2;" : "=r"(l), "=r"(h) : "l"(v));
    lo = __uint_as_float(l); hi = __uint_as_float(h);
}
__device__ __forceinline__ u64p f2fma(u64p a, u64p b, u64p c) {
    u64p d;
    asm("fma.rn.f32x2 %0, %1, %2, %3;" : "=l"(d) : "l"(a), "l"(b), "l"(c));
    return d;
}
__device__ __forceinline__ u64p f2mul(u64p a, u64p b) {
    u64p d;
    asm("mul.rn.f32x2 %0, %1, %2;" : "=l"(d) : "l"(a), "l"(b));
    return d;
}
__device__ __forceinline__ u64p f2add(u64p a, u64p b) {
    u64p d;
    asm("add.rn.f32x2 %0, %1, %2;" : "=l"(d) : "l"(a), "l"(b));
    return d;
}
__device__ __forceinline__ float ex2a(float x) {
    float r; asm("ex2.approx.f32 %0, %1;" : "=f"(r) : "f"(x)); return r;
}
__device__ __forceinline__ float rcpa(float x) {
    float r; asm("rcp.approx.f32 %0, %1;" : "=f"(r) : "f"(x)); return r;
}

__global__ void __launch_bounds__(TPB, 1)
fr_kernel(const float* __restrict__ cur,   // [T, B]
          const float* __restrict__ fs0,   // [B]
          const float* __restrict__ av,    // [N]
          const float* __restrict__ bv,    // [N]
          const float* __restrict__ wv,    // [N]
          const float* __restrict__ dsv,   // [N]
          const float* __restrict__ pc,    // [6]
          const float* __restrict__ gbp,   // [1]
          float* __restrict__ out,         // [T, B]
          int T, int B)
{
    int tid = blockIdx.x * TPB + threadIdx.x;
    int chain = tid >> 2;        // one chain per 4 lanes
    int r = tid & 3;
    if (chain >= B) return;
    int nb = r * 16;             // 16 neurons = 8 packed pairs per lane

    // Polynomial coefficients, squared per reference, K = 2*log2(e) folded in.
    const float K = 2.885390081777927f;
    float C0 = K * pc[0] * pc[0], C1 = K * pc[1] * pc[1], C2 = K * pc[2] * pc[2];
    float C3 = K * pc[3] * pc[3], C4 = K * pc[4] * pc[4], C5 = K * pc[5] * pc[5];
    float gb = gbp[0] * 0.01f;

    // Per-lane constants. A' = a*w/100, B' = 10*b*w, D = 1-ds.
    // D2A = D^2∘A', D3B = D^3∘B'.
    u64p D[8], D2A[8], D3B[8], V[8];   // V here holds Vt (f-deferred state)
    float sap = 0.f, sbp = 0.f, sdap = 0.f, sdbp = 0.f, sd2bp = 0.f;
    #pragma unroll
    for (int j = 0; j < 8; j++) {
        int n0 = nb + 2 * j;
        float w0 = wv[n0],            w1 = wv[n0 + 1];
        float d0 = 1.f - dsv[n0],     d1 = 1.f - dsv[n0 + 1];
        float a0 = av[n0] * w0 * 0.01f, a1 = av[n0 + 1] * w1 * 0.01f;
        float b0 = 10.f * bv[n0] * w0,  b1 = 10.f * bv[n0 + 1] * w1;
        D[j]   = pk2(d0, d1);
        D2A[j] = pk2(d0 * d0 * a0, d1 * d1 * a1);
        D3B[j] = pk2(d0 * d0 * d0 * b0, d1 * d1 * d1 * b1);
        V[j]   = 0ull;
        sap   += a0 + a1;
        sbp   += b0 + b1;
        sdap  += d0 * a0 + d1 * a1;
        sdbp  += d0 * b0 + d1 * b1;
        sd2bp += d0 * d0 * b0 + d1 * d1 * b1;
    }
    #pragma unroll
    for (int m = 1; m <= 2; m <<= 1) {
        sap   += __shfl_xor_sync(0xffffffffu, sap,   m);
        sbp   += __shfl_xor_sync(0xffffffffu, sbp,   m);
        sdap  += __shfl_xor_sync(0xffffffffu, sdap,  m);
        sdbp  += __shfl_xor_sync(0xffffffffu, sdbp,  m);
        sd2bp += __shfl_xor_sync(0xffffffffu, sd2bp, m);
    }
    const float SA = sap, SB = sbp, SDA = sdap, SDB = sdbp, SD2B = sd2bp;

    float f1  = fs0[chain];      // f(t-1)
    float fx2 = 0.f;             // f(t-2)
    float fx3 = 0.f;             // f(t-3)
    float Wprev = 0.f;           // Sum(Vt(t-2)) at top of body t
    float pend  = 0.f;           // in-lane tree sum of Vt(t-1), awaiting shfls
    float cprev = 0.f;           // c_{t-1} (raw, always >=8 steps post-load)

    const float* cp = cur + chain;         // initial ring fill
    const float* lp = cp + (size_t)8 * B;  // prefetch pointer -> c_{t+8}
    float* op = out + chain;

    // Prefetch ring: cb[i] = c_i (raw only; derived terms computed at use
    // time, 8 steps after the load).
    float cb[8];
    #pragma unroll
    for (int i = 0; i < 8; i++) cb[i] = cp[(size_t)i * B];

    // One step. craw = c_t (loaded 8 steps ago). phi is LAST; everything
    // before it depends only on state >= 1 body old.
    #define FR_STEP(craw, kk)                                                  \
    {                                                                          \
        /* c-terms (operands 8 steps old) */                                   \
        float cpre = fmaf((craw), SA, fmaf(cprev, SDA, -gb));                  \
        u64p c2   = pk2((craw), (craw));                                       \
        u64p fx2r = pk2(fx2, fx2);           /* f(t-2): one body old */        \
        /* shfl1 on last body's tree sum -- issued early, consumed late */     \
        float sh1 = __shfl_xor_sync(0xffffffffu, pend, 1);                     \
        /* wide: Vt(t) = D∘Vt + c*D2A + f(t-2)*D3B  (no fn dependence!) */     \
        V[0] = f2fma(D[0], V[0], f2fma(D3B[0], fx2r, f2mul(D2A[0], c2)));      \
        V[1] = f2fma(D[1], V[1], f2fma(D3B[1], fx2r, f2mul(D2A[1], c2)));      \
        V[2] = f2fma(D[2], V[2], f2fma(D3B[2], fx2r, f2mul(D2A[2], c2)));      \
        V[3] = f2fma(D[3], V[3], f2fma(D3B[3], fx2r, f2mul(D2A[3], c2)));      \
        V[4] = f2fma(D[4], V[4], f2fma(D3B[4], fx2r, f2mul(D2A[4], c2)));      \
        V[5] = f2fma(D[5], V[5], f2fma(D3B[5], fx2r, f2mul(D2A[5], c2)));      \
        V[6] = f2fma(D[6], V[6], f2fma(D3B[6], fx2r, f2mul(D2A[6], c2)));      \
        V[7] = f2fma(D[7], V[7], f2fma(D3B[7], fx2r, f2mul(D2A[7], c2)));      \
        /* complete last body's reduction: shfl2 covered by tree below */      \
        float sp = pend + sh1;                                                 \
        float sh2 = __shfl_xor_sync(0xffffffffu, sp, 2);                       \
        /* tree over fresh Vt(t) -> pend (shfl'd NEXT body) */                 \
        u64p g0 = f2add(f2add(V[0], V[1]), f2add(V[2], V[3]));                 \
        u64p g1 = f2add(f2add(V[4], V[5]), f2add(V[6], V[7]));                 \
        u64p gt = f2add(g0, g1);                                               \
        float lo, hi; upk2(gt, lo, hi);                                        \
        float newpend = lo + hi;                                               \
        float Wnew = sp + sh2;               /* = Sum(Vt(t-1)) */              \
        /* phi LAST: only consumer of fn(t-1), produced ~full body ago */      \
        float base = fmaf(fx3, SD2B, Wprev + cpre);                            \
        base = fmaf(fx2, SDB, base);                                           \
        float x = fmaf(f1, SB, base);                                          \
        float x2 = x * x;                                                      \
        float e01 = fmaf(C1, x, C0);                                           \
        float e23 = fmaf(C3, x, C2);                                           \
        float e45 = fmaf(C5, x, C4);                                           \
        float x4 = x2 * x2;                                                    \
        float q  = fmaf(x2, e23, e01);                                         \
        q = fmaf(x4, e45, q);                          /* q = K*poly(x) */     \
        float e = ex2a(q);                                                     \
        float fn = fmaf(rcpa(e + 1.f), -400.f, 200.f);                         \
        fn = fmaxf(fn, 0.f);                                                   \
        if (r == 0) op[(size_t)(kk) * B] = fn;                                 \
        Wprev = Wnew;                                                          \
        pend  = newpend;                                                       \
        cprev = (craw);                                                        \
        fx3 = fx2;                                                             \
        fx2 = f1;                                                              \
        f1  = fn;                                                              \
    }

    // Main loop: steps [0, T-8). Refill is a pure register write from LDG;
    // the loaded value is untouched for 8 steps.
    for (int t = 0; t < T - 8; t += 8) {
        #pragma unroll
        for (int k = 0; k < 8; k++) {
            float craw = cb[k];
            cb[k] = lp[(size_t)k * B];
            FR_STEP(craw, k)
        }
        lp += (size_t)8 * B;
        op += (size_t)8 * B;
    }
    // Epilogue: last 8 steps, no loads
    #pragma unroll
    for (int k = 0; k < 8; k++) {
        FR_STEP(cb[k], k)
    }
    #undef FR_STEP
}

extern "C" void kernel_launch(void* const* d_in, const int* in_sizes, int n_in,
                              void* d_out, int out_size) {
    const float* cur = (const float*)d_in[0];   // currents [T*B]
    const float* fs0 = (const float*)d_in[1];   // [B]
    const float* av  = (const float*)d_in[2];   // [N]
    const float* bv  = (const float*)d_in[3];   // [N]
    const float* wv  = (const float*)d_in[4];   // [N,1]
    const float* dsv = (const float*)d_in[5];   // [N]
    const float* pc  = (const float*)d_in[6];   // [DEG+1]
    const float* gbp = (const float*)d_in[7];   // scalar

    int B = in_sizes[1];
    int T = in_sizes[0] / B;

    int threads = B * 4;                        // 4 lanes per chain
    int blocks = (threads + TPB - 1) / TPB;
    fr_kernel<<<blocks, TPB>>>(cur, fs0, av, bv, wv, dsv, pc, gbp,
                               (float*)d_out, T, B);
}